// round 1
// baseline (speedup 1.0000x reference)
#include <cuda_runtime.h>

// Problem dims (fixed by dataset): N=30000, F=16, S=8, H=16, E=300000
#define NMAX 30000
#define EMAX 300000

// Scratch (no allocations allowed): g[n][10-ish slices][16]
// g row = 9 slices (8 from Wk, 1 from bk) * 16 h = 144 floats = 576 B
__device__ float g_buf[NMAX * 144];
__device__ float agg_buf[NMAX * 16];
__device__ unsigned pooled_bits[16];

// ---------------------------------------------------------------------------
// Kernel P: per-node precompute.
//   g[n,s,h]   = sum_f x[n,f] * Wk[s, f*16+h]   (s = 0..7)
//   g[n,8,h]   = sum_f x[n,f] * bk[f*16+h]      (bias slice, virtual e=1)
//   agg[n,h]   = sum_f x[n,f] * Wr[f,h] + br[h] (init of aggregation buffer)
// Thread = (node, h): block 256 = 16 nodes x 16 h.
// ---------------------------------------------------------------------------
__global__ void __launch_bounds__(256) node_pre(const float* __restrict__ x,
                                                const float* __restrict__ Wk,
                                                const float* __restrict__ bk,
                                                const float* __restrict__ Wr,
                                                const float* __restrict__ br,
                                                int N)
{
    // Ms layout: [t][f][h] flat, t=0..7 Wk slices, t=8 bk, t=9 Wr
    __shared__ float Ms[2560];
    __shared__ float brs[16];
    __shared__ float xs[256];

    int tid = threadIdx.x;
    for (int i = tid; i < 2048; i += 256) Ms[i] = Wk[i];          // Wk is [s][f*16+h]
    Ms[2048 + tid] = bk[tid];                                     // bk [f*16+h]
    Ms[2304 + tid] = Wr[tid];                                     // Wr [f][h]
    if (tid < 16) brs[tid] = br[tid];

    int nb = blockIdx.x * 16;
    int xi = nb * 16 + tid;
    xs[tid] = (xi < N * 16) ? x[xi] : 0.0f;

    if (blockIdx.x == 0 && tid < 16) pooled_bits[tid] = 0u;       // min key
    __syncthreads();

    int local_n = tid >> 4;
    int h = tid & 15;
    int n = nb + local_n;
    if (n >= N) return;

    float acc[10];
#pragma unroll
    for (int t = 0; t < 10; t++) acc[t] = 0.0f;

#pragma unroll
    for (int f = 0; f < 16; f++) {
        float xv = xs[local_n * 16 + f];
#pragma unroll
        for (int t = 0; t < 10; t++)
            acc[t] += xv * Ms[t * 256 + f * 16 + h];
    }

    float* gr = g_buf + (size_t)n * 144 + h;
#pragma unroll
    for (int s = 0; s < 9; s++) gr[s * 16] = acc[s];
    agg_buf[n * 16 + h] = acc[9] + brs[h];
}

// ---------------------------------------------------------------------------
// Kernel E: per-edge gather + tiny dot + scatter-add.
// 8 lanes per edge, lane j owns h = {2j, 2j+1}.
//   msg[e,h] = sum_{s=0..8} es[s] * g[src[e], s, h]    (es[8] = 1.0 bias slice)
//   red.add into agg[dst[e], h]
// g loads: for fixed s, the 8 lanes of a group read 64 contiguous bytes.
// ---------------------------------------------------------------------------
__global__ void __launch_bounds__(256) edge_kernel(const float* __restrict__ e,
                                                   const int* __restrict__ src,
                                                   const int* __restrict__ dst,
                                                   int E)
{
    int t = blockIdx.x * 256 + threadIdx.x;
    int gid = t >> 3;
    if (gid >= E) return;
    int j = t & 7;

    int sn = src[gid];
    int dn = dst[gid];

    const float4* ep = (const float4*)(e + (size_t)gid * 8);
    float4 e0 = ep[0];
    float4 e1 = ep[1];
    float es[9] = { e0.x, e0.y, e0.z, e0.w, e1.x, e1.y, e1.z, e1.w, 1.0f };

    const float2* gr = (const float2*)(g_buf + (size_t)sn * 144) + j;
    float ax = 0.0f, ay = 0.0f;
#pragma unroll
    for (int s = 0; s < 9; s++) {
        float2 w = gr[s * 8];
        ax += es[s] * w.x;
        ay += es[s] * w.y;
    }

    float* out = agg_buf + (size_t)dn * 16 + 2 * j;
    asm volatile("red.global.add.v2.f32 [%0], {%1, %2};"
                 :: "l"(out), "f"(ax), "f"(ay) : "memory");
}

// ---------------------------------------------------------------------------
// Kernel C: relu + BN + block max-reduce + global atomicMax (ordered-uint keys)
// Thread = node, holds all 16 h values.
// ---------------------------------------------------------------------------
__global__ void __launch_bounds__(256) node_post(const float* __restrict__ gamma,
                                                 const float* __restrict__ beta,
                                                 const float* __restrict__ mmean,
                                                 const float* __restrict__ mvar,
                                                 int N)
{
    __shared__ float wmax[8][16];
    int n = blockIdx.x * 256 + threadIdx.x;

    float v[16];
    if (n < N) {
        const float4* ar = (const float4*)(agg_buf + (size_t)n * 16);
#pragma unroll
        for (int q = 0; q < 4; q++) {
            float4 a = ar[q];
            v[4 * q + 0] = a.x; v[4 * q + 1] = a.y;
            v[4 * q + 2] = a.z; v[4 * q + 3] = a.w;
        }
#pragma unroll
        for (int h = 0; h < 16; h++) {
            float sc = gamma[h] * rsqrtf(mvar[h] + 1e-3f);
            float sh = beta[h] - mmean[h] * sc;
            v[h] = fmaxf(v[h], 0.0f) * sc + sh;
        }
    } else {
#pragma unroll
        for (int h = 0; h < 16; h++) v[h] = -__int_as_float(0x7f800000); // -inf
    }

    // butterfly max across the warp (per h)
#pragma unroll
    for (int off = 16; off >= 1; off >>= 1) {
#pragma unroll
        for (int h = 0; h < 16; h++)
            v[h] = fmaxf(v[h], __shfl_xor_sync(0xffffffffu, v[h], off));
    }

    int wid = threadIdx.x >> 5;
    if ((threadIdx.x & 31) == 0) {
#pragma unroll
        for (int h = 0; h < 16; h++) wmax[wid][h] = v[h];
    }
    __syncthreads();

    if (threadIdx.x < 16) {
        int h = threadIdx.x;
        float m = wmax[0][h];
#pragma unroll
        for (int w = 1; w < 8; w++) m = fmaxf(m, wmax[w][h]);
        unsigned b = __float_as_uint(m);
        unsigned k = (b & 0x80000000u) ? ~b : (b | 0x80000000u); // order-preserving
        atomicMax(&pooled_bits[h], k);
    }
}

// ---------------------------------------------------------------------------
// Kernel F: decode pooled max, out[1,3] = pooled @ Wd + bd
// ---------------------------------------------------------------------------
__global__ void finalize(const float* __restrict__ Wd,
                         const float* __restrict__ bd,
                         float* __restrict__ out)
{
    __shared__ float pooled[16];
    int t = threadIdx.x;
    if (t < 16) {
        unsigned k = pooled_bits[t];
        unsigned b = (k & 0x80000000u) ? (k ^ 0x80000000u) : ~k;
        pooled[t] = __uint_as_float(b);
    }
    __syncthreads();
    if (t < 3) {
        float s = bd[t];
#pragma unroll
        for (int h = 0; h < 16; h++) s += pooled[h] * Wd[h * 3 + t];
        out[t] = s;
    }
}

// ---------------------------------------------------------------------------
extern "C" void kernel_launch(void* const* d_in, const int* in_sizes, int n_in,
                              void* d_out, int out_size)
{
    const float* x     = (const float*)d_in[0];
    const float* e     = (const float*)d_in[1];
    const int*   src   = (const int*)d_in[2];
    const int*   dst   = (const int*)d_in[3];
    const float* Wk    = (const float*)d_in[4];
    const float* bk    = (const float*)d_in[5];
    const float* Wr    = (const float*)d_in[6];
    const float* br    = (const float*)d_in[7];
    const float* gamma = (const float*)d_in[8];
    const float* beta  = (const float*)d_in[9];
    const float* mmean = (const float*)d_in[10];
    const float* mvar  = (const float*)d_in[11];
    const float* Wd    = (const float*)d_in[12];
    const float* bd    = (const float*)d_in[13];

    int N = in_sizes[0] / 16;   // F = 16
    int E = in_sizes[2];

    node_pre<<<(N + 15) / 16, 256>>>(x, Wk, bk, Wr, br, N);
    edge_kernel<<<(E * 8 + 255) / 256, 256>>>(e, src, dst, E);
    node_post<<<(N + 255) / 256, 256>>>(gamma, beta, mmean, mvar, N);
    finalize<<<1, 32>>>(Wd, bd, (float*)d_out);
}

// round 2
// speedup vs baseline: 1.1127x; 1.1127x over previous
#include <cuda_runtime.h>
#include <cuda_fp16.h>

// Problem dims (fixed by dataset): N=30000, F=16, S=8, H=16, E=300000
#define NMAX 30016   // padded to multiple of 64
#define EMAX 300000

// Scratch: g in fp16: [n][9 slices][16 h]  (slice 8 = bias from bk)
__device__ __half   g_h[(size_t)NMAX * 144];
__device__ float    agg_buf[(size_t)NMAX * 16];
__device__ unsigned pooled_bits[16];
__device__ unsigned finish_count;

#define FMA2(acc, a, b) \
    asm("fma.rn.f32x2 %0, %1, %2, %3;" : "=l"(acc) : "l"(a), "l"(b), "l"(acc))
#define PACK2(dst, v) \
    asm("mov.b64 %0, {%1, %1};" : "=l"(dst) : "f"(v))
#define UNPACK2(lo, hi, v) \
    asm("mov.b64 {%0, %1}, %2;" : "=f"(lo), "=f"(hi) : "l"(v))

// ---------------------------------------------------------------------------
// Kernel P: per-node precompute (packed f32x2 math, 2 nodes per thread).
//   g[n,s,h]   = sum_f x[n,f] * Wk[s, f*16+h]   (s = 0..7)
//   g[n,8,h]   = sum_f x[n,f] * bk[f*16+h]      (bias slice, virtual e=1)
//   agg[n,h]   = sum_f x[n,f] * Wr[f,h] + br[h]
// Block = 256 threads = 32 node-slots x 8 h-pairs; covers 64 nodes
// (slot and slot+32). Weights live in shared, read as 8B broadcasts.
// ---------------------------------------------------------------------------
__global__ void __launch_bounds__(256) node_pre(const float* __restrict__ x,
                                                const float* __restrict__ Wk,
                                                const float* __restrict__ bk,
                                                const float* __restrict__ Wr,
                                                const float* __restrict__ br,
                                                int N)
{
    __shared__ float Ms[2560];   // [t][f][h], t=0..7 Wk, t=8 bk, t=9 Wr
    __shared__ float xs[1024];   // 64 nodes x 16 f
    __shared__ float brs[16];

    int tid = threadIdx.x;
    for (int i = tid; i < 2048; i += 256) Ms[i] = Wk[i];
    Ms[2048 + tid] = bk[tid];
    Ms[2304 + tid] = Wr[tid];
    if (tid < 16) brs[tid] = br[tid];

    int nb = blockIdx.x * 64;
    for (int i = tid; i < 1024; i += 256) {
        int xi = nb * 16 + i;
        xs[i] = (xi < N * 16) ? x[xi] : 0.0f;
    }
    if (blockIdx.x == 0) {
        if (tid < 16) pooled_bits[tid] = 0u;
        if (tid == 0) finish_count = 0u;
    }
    __syncthreads();

    int j = tid & 7;          // h-pair index: h = 2j, 2j+1
    int slot = tid >> 3;      // 0..31

    unsigned long long acc[2][10];
#pragma unroll
    for (int u = 0; u < 2; u++)
#pragma unroll
        for (int t = 0; t < 10; t++) acc[u][t] = 0ull;

    const unsigned long long* Ms2 = (const unsigned long long*)Ms;

#pragma unroll
    for (int f = 0; f < 16; f++) {
        float xa = xs[slot * 16 + f];
        float xb = xs[(slot + 32) * 16 + f];
        unsigned long long xa2, xb2;
        PACK2(xa2, xa);
        PACK2(xb2, xb);
#pragma unroll
        for (int t = 0; t < 10; t++) {
            unsigned long long w2 = Ms2[t * 128 + f * 8 + j];
            FMA2(acc[0][t], xa2, w2);
            FMA2(acc[1][t], xb2, w2);
        }
    }

#pragma unroll
    for (int u = 0; u < 2; u++) {
        int n = nb + slot + u * 32;
        if (n >= N) continue;
        __half2* gr = (__half2*)g_h + (size_t)n * 72 + j;
#pragma unroll
        for (int s = 0; s < 9; s++) {
            float lo, hi;
            UNPACK2(lo, hi, acc[u][s]);
            gr[s * 8] = __floats2half2_rn(lo, hi);
        }
        float lo, hi;
        UNPACK2(lo, hi, acc[u][9]);
        float2 a2 = make_float2(lo + brs[2 * j], hi + brs[2 * j + 1]);
        *(float2*)(agg_buf + (size_t)n * 16 + 2 * j) = a2;
    }
}

// ---------------------------------------------------------------------------
// Kernel E: per-edge gather (fp16 g) + tiny dot + vector red scatter.
// 8 lanes per edge, lane j owns h = {2j, 2j+1}.
// ---------------------------------------------------------------------------
__global__ void __launch_bounds__(256) edge_kernel(const float* __restrict__ e,
                                                   const int* __restrict__ src,
                                                   const int* __restrict__ dst,
                                                   int E)
{
    int t = blockIdx.x * 256 + threadIdx.x;
    int gid = t >> 3;
    if (gid >= E) return;
    int j = t & 7;

    int sn = src[gid];
    int dn = dst[gid];

    const float4* ep = (const float4*)(e + (size_t)gid * 8);
    float4 e0 = ep[0];
    float4 e1 = ep[1];
    float es[9] = { e0.x, e0.y, e0.z, e0.w, e1.x, e1.y, e1.z, e1.w, 1.0f };

    const __half2* gr = (const __half2*)g_h + (size_t)sn * 72 + j;
    float ax = 0.0f, ay = 0.0f;
#pragma unroll
    for (int s = 0; s < 9; s++) {
        float2 w = __half22float2(gr[s * 8]);
        ax += es[s] * w.x;
        ay += es[s] * w.y;
    }

    float* out = agg_buf + (size_t)dn * 16 + 2 * j;
    asm volatile("red.global.add.v2.f32 [%0], {%1, %2};"
                 :: "l"(out), "f"(ax), "f"(ay) : "memory");
}

// ---------------------------------------------------------------------------
// Kernel C: relu + BN + block max-reduce + atomicMax; LAST block also does
// the final dense (fused finalize).
// ---------------------------------------------------------------------------
__global__ void __launch_bounds__(256) node_post(const float* __restrict__ gamma,
                                                 const float* __restrict__ beta,
                                                 const float* __restrict__ mmean,
                                                 const float* __restrict__ mvar,
                                                 const float* __restrict__ Wd,
                                                 const float* __restrict__ bd,
                                                 float* __restrict__ out,
                                                 int N)
{
    __shared__ float wmax[8][16];
    __shared__ bool is_last;
    int n = blockIdx.x * 256 + threadIdx.x;

    float v[16];
    if (n < N) {
        const float4* ar = (const float4*)(agg_buf + (size_t)n * 16);
#pragma unroll
        for (int q = 0; q < 4; q++) {
            float4 a = ar[q];
            v[4 * q + 0] = a.x; v[4 * q + 1] = a.y;
            v[4 * q + 2] = a.z; v[4 * q + 3] = a.w;
        }
#pragma unroll
        for (int h = 0; h < 16; h++) {
            float sc = gamma[h] * rsqrtf(mvar[h] + 1e-3f);
            float sh = beta[h] - mmean[h] * sc;
            v[h] = fmaxf(v[h], 0.0f) * sc + sh;
        }
    } else {
#pragma unroll
        for (int h = 0; h < 16; h++) v[h] = -__int_as_float(0x7f800000); // -inf
    }

#pragma unroll
    for (int off = 16; off >= 1; off >>= 1) {
#pragma unroll
        for (int h = 0; h < 16; h++)
            v[h] = fmaxf(v[h], __shfl_xor_sync(0xffffffffu, v[h], off));
    }

    int wid = threadIdx.x >> 5;
    if ((threadIdx.x & 31) == 0) {
#pragma unroll
        for (int h = 0; h < 16; h++) wmax[wid][h] = v[h];
    }
    __syncthreads();

    if (threadIdx.x < 16) {
        int h = threadIdx.x;
        float m = wmax[0][h];
#pragma unroll
        for (int w = 1; w < 8; w++) m = fmaxf(m, wmax[w][h]);
        unsigned b = __float_as_uint(m);
        unsigned k = (b & 0x80000000u) ? ~b : (b | 0x80000000u);
        atomicMax(&pooled_bits[h], k);
    }

    // last-block finalize
    __threadfence();
    if (threadIdx.x == 0) {
        unsigned c = atomicAdd(&finish_count, 1u);
        is_last = (c == gridDim.x - 1);
    }
    __syncthreads();
    if (!is_last) return;

    __threadfence();
    __shared__ float pooled[16];
    if (threadIdx.x < 16) {
        unsigned k = atomicAdd(&pooled_bits[threadIdx.x], 0u);  // L2-coherent read
        unsigned b = (k & 0x80000000u) ? (k ^ 0x80000000u) : ~k;
        pooled[threadIdx.x] = __uint_as_float(b);
    }
    __syncthreads();
    if (threadIdx.x < 3) {
        float s = bd[threadIdx.x];
#pragma unroll
        for (int h = 0; h < 16; h++) s += pooled[h] * Wd[h * 3 + threadIdx.x];
        out[threadIdx.x] = s;
    }
}

// ---------------------------------------------------------------------------
extern "C" void kernel_launch(void* const* d_in, const int* in_sizes, int n_in,
                              void* d_out, int out_size)
{
    const float* x     = (const float*)d_in[0];
    const float* e     = (const float*)d_in[1];
    const int*   src   = (const int*)d_in[2];
    const int*   dst   = (const int*)d_in[3];
    const float* Wk    = (const float*)d_in[4];
    const float* bk    = (const float*)d_in[5];
    const float* Wr    = (const float*)d_in[6];
    const float* br    = (const float*)d_in[7];
    const float* gamma = (const float*)d_in[8];
    const float* beta  = (const float*)d_in[9];
    const float* mmean = (const float*)d_in[10];
    const float* mvar  = (const float*)d_in[11];
    const float* Wd    = (const float*)d_in[12];
    const float* bd    = (const float*)d_in[13];

    int N = in_sizes[0] / 16;   // F = 16
    int E = in_sizes[2];

    node_pre<<<(N + 63) / 64, 256>>>(x, Wk, bk, Wr, br, N);
    edge_kernel<<<(E * 8 + 255) / 256, 256>>>(e, src, dst, E);
    node_post<<<(N + 255) / 256, 256>>>(gamma, beta, mmean, mvar, Wd, bd,
                                        (float*)d_out, N);
}